// round 3
// baseline (speedup 1.0000x reference)
#include <cuda_runtime.h>

#define NSP 4096
#define CDIM 256
#define BQ 64
#define BK 64
#define NB 8

// Scratch for projected Q, K, V : [B][C][N] fp32 (33.5 MB each)
__device__ float g_Q[(size_t)NB * CDIM * NSP];
__device__ float g_K[(size_t)NB * CDIM * NSP];
__device__ float g_V[(size_t)NB * CDIM * NSP];

typedef unsigned long long u64;

__device__ __forceinline__ u64 ffma2(u64 a, u64 b, u64 c) {
    u64 d;
    asm("fma.rn.f32x2 %0, %1, %2, %3;" : "=l"(d) : "l"(a), "l"(b), "l"(c));
    return d;
}
__device__ __forceinline__ u64 fmul2(u64 a, u64 b) {
    u64 d;
    asm("mul.rn.f32x2 %0, %1, %2;" : "=l"(d) : "l"(a), "l"(b));
    return d;
}
__device__ __forceinline__ u64 pack2(float lo, float hi) {
    u64 d;
    asm("mov.b64 %0, {%1, %2};" : "=l"(d) : "f"(lo), "f"(hi));
    return d;
}
__device__ __forceinline__ float2 unpack2(u64 v) {
    float lo, hi;
    asm("mov.b64 {%0, %1}, %2;" : "=f"(lo), "=f"(hi) : "l"(v));
    return make_float2(lo, hi);
}

// ---------------------------------------------------------------------------
// Kernel 1: 1x1-conv projections.  Out[b][o][n] = sum_c W[o][c] * X[b][c][n] + bias[o]
// grid: (N/64, B, 12)  z: proj = z>>2 (0:Q,1:K,2:V), o-tile = z&3.  256 threads.
// ---------------------------------------------------------------------------
__global__ __launch_bounds__(256) void proj_kernel(
    const float* __restrict__ x, const float* __restrict__ attr,
    const float* __restrict__ Wq, const float* __restrict__ bq,
    const float* __restrict__ Wk, const float* __restrict__ bk,
    const float* __restrict__ Wv, const float* __restrict__ bv)
{
    __shared__ __align__(16) float Xs[32 * 64];
    __shared__ __align__(16) float Wt[32 * 68];

    const int tid = threadIdx.x;
    const int tx = tid & 15, ty = tid >> 4;
    const int n0 = blockIdx.x * 64;
    const int bb = blockIdx.y;
    const int z = blockIdx.z;
    const int proj = z >> 2;
    const int o0 = (z & 3) * 64;

    const float* X;
    const float* W;
    const float* bias;
    float* dst;
    if (proj == 0)      { X = x;    W = Wq; bias = bq; dst = g_Q; }
    else if (proj == 1) { X = attr; W = Wk; bias = bk; dst = g_K; }
    else                { X = attr; W = Wv; bias = bv; dst = g_V; }

    const float* Xb = X + (size_t)bb * CDIM * NSP;

    u64 acc[4][2];
    #pragma unroll
    for (int r = 0; r < 4; r++) {
        float bv0 = bias[o0 + 4 * ty + r];
        acc[r][0] = pack2(bv0, bv0);
        acc[r][1] = acc[r][0];
    }

    for (int ck = 0; ck < 8; ck++) {
        const int c0 = ck * 32;
        __syncthreads();
        // X chunk [32 c][64 n] -> Xs, coalesced
        {
            int row = tid >> 3, col = (tid & 7) * 4;
            const float* src = Xb + (size_t)(c0 + row) * NSP + n0;
            *(float4*)&Xs[row * 64 + col]      = *(const float4*)&src[col];
            *(float4*)&Xs[row * 64 + col + 32] = *(const float4*)&src[col + 32];
        }
        // W chunk transposed: Wt[cc][oo] = W[o0+oo][c0+cc]
        {
            int oo = tid >> 2, cc0 = (tid & 3) * 8;
            const float* src = W + (size_t)(o0 + oo) * CDIM + c0 + cc0;
            float4 a = *(const float4*)&src[0];
            float4 c4 = *(const float4*)&src[4];
            Wt[(cc0 + 0) * 68 + oo] = a.x;
            Wt[(cc0 + 1) * 68 + oo] = a.y;
            Wt[(cc0 + 2) * 68 + oo] = a.z;
            Wt[(cc0 + 3) * 68 + oo] = a.w;
            Wt[(cc0 + 4) * 68 + oo] = c4.x;
            Wt[(cc0 + 5) * 68 + oo] = c4.y;
            Wt[(cc0 + 6) * 68 + oo] = c4.z;
            Wt[(cc0 + 7) * 68 + oo] = c4.w;
        }
        __syncthreads();

        #pragma unroll 8
        for (int cc = 0; cc < 32; cc++) {
            float4 wv = *(float4*)&Wt[cc * 68 + 4 * ty];
            ulonglong2 xv = *(ulonglong2*)&Xs[cc * 64 + 4 * tx];
            u64 w0 = pack2(wv.x, wv.x), w1 = pack2(wv.y, wv.y);
            u64 w2 = pack2(wv.z, wv.z), w3 = pack2(wv.w, wv.w);
            acc[0][0] = ffma2(w0, xv.x, acc[0][0]); acc[0][1] = ffma2(w0, xv.y, acc[0][1]);
            acc[1][0] = ffma2(w1, xv.x, acc[1][0]); acc[1][1] = ffma2(w1, xv.y, acc[1][1]);
            acc[2][0] = ffma2(w2, xv.x, acc[2][0]); acc[2][1] = ffma2(w2, xv.y, acc[2][1]);
            acc[3][0] = ffma2(w3, xv.x, acc[3][0]); acc[3][1] = ffma2(w3, xv.y, acc[3][1]);
        }
    }

    #pragma unroll
    for (int r = 0; r < 4; r++) {
        float2 a = unpack2(acc[r][0]);
        float2 c2 = unpack2(acc[r][1]);
        float4 res = make_float4(a.x, a.y, c2.x, c2.y);
        *(float4*)&dst[((size_t)bb * CDIM + o0 + 4 * ty + r) * NSP + n0 + 4 * tx] = res;
    }
}

// ---------------------------------------------------------------------------
// Kernel 2: flash attention (no scale) + residual add.
// grid: (N/BQ, B), 256 threads (16x16).  1 CTA/SM (209 KB smem).
//   S[i][j] = sum_c Q[c][i] K[c][j] ; softmax over j (online) ;
//   O[i][c] = sum_j P[i][j] V[c][j] ; out = O/l + x
// ---------------------------------------------------------------------------
#define SM_Q  0
#define SM_K  16384
#define SM_V  32768
#define SM_P  49152
#define SM_FLOATS (49152 + 64 * 68)
#define SM_BYTES  (SM_FLOATS * 4)

__global__ __launch_bounds__(256) void attn_kernel(
    const float* __restrict__ x, float* __restrict__ out)
{
    extern __shared__ __align__(16) float sm[];
    float* Qs = sm + SM_Q;   // [256 c][64 i]
    float* Ks = sm + SM_K;   // [256 c][64 j]
    float* Vt = sm + SM_V;   // [64 j][256 c]
    float* Pt = sm + SM_P;   // [64 j][68] (i fast)

    const int tid = threadIdx.x;
    const int tx = tid & 15, ty = tid >> 4;
    const int bb = blockIdx.y;
    const int n0 = blockIdx.x * BQ;

    const float* Qg = g_Q + (size_t)bb * CDIM * NSP;
    const float* Kg = g_K + (size_t)bb * CDIM * NSP;
    const float* Vg = g_V + (size_t)bb * CDIM * NSP;

    // Load Q tile [256][64], coalesced
    #pragma unroll
    for (int it = 0; it < 16; it++) {
        int c = it * 16 + ty;
        *(float4*)&Qs[c * 64 + 4 * tx] =
            *(const float4*)&Qg[(size_t)c * NSP + n0 + 4 * tx];
    }

    u64 Oa[4][4][2];
    #pragma unroll
    for (int r = 0; r < 4; r++)
        #pragma unroll
        for (int pp = 0; pp < 4; pp++) { Oa[r][pp][0] = 0ULL; Oa[r][pp][1] = 0ULL; }

    float m[4], l[4];
    #pragma unroll
    for (int r = 0; r < 4; r++) { m[r] = -1e30f; l[r] = 0.0f; }

    for (int kt = 0; kt < NSP / BK; kt++) {
        const int k0 = kt * BK;
        __syncthreads();  // previous iteration done with Ks/Vt/Pt (also covers Q load)

        // K tile [256 c][64 j]
        #pragma unroll
        for (int it = 0; it < 16; it++) {
            int c = it * 16 + ty;
            *(float4*)&Ks[c * 64 + 4 * tx] =
                *(const float4*)&Kg[(size_t)c * NSP + k0 + 4 * tx];
        }
        // V tile transposed -> Vt[j][c]; conflict-free stores (lanes vary c)
        {
            const float* src = Vg + (size_t)tid * NSP + k0;
            #pragma unroll
            for (int j4 = 0; j4 < 16; j4++) {
                float4 v = *(const float4*)&src[4 * j4];
                Vt[(4 * j4 + 0) * 256 + tid] = v.x;
                Vt[(4 * j4 + 1) * 256 + tid] = v.y;
                Vt[(4 * j4 + 2) * 256 + tid] = v.z;
                Vt[(4 * j4 + 3) * 256 + tid] = v.w;
            }
        }
        __syncthreads();

        // ---- S = Q^T K : thread tile i=4ty+r, j=4tx+(2h+e) ----
        u64 Sa[4][2];
        #pragma unroll
        for (int r = 0; r < 4; r++) { Sa[r][0] = 0ULL; Sa[r][1] = 0ULL; }

        #pragma unroll 8
        for (int c = 0; c < CDIM; c++) {
            float4 qv = *(float4*)&Qs[c * 64 + 4 * ty];
            ulonglong2 kv = *(ulonglong2*)&Ks[c * 64 + 4 * tx];
            u64 q0 = pack2(qv.x, qv.x), q1 = pack2(qv.y, qv.y);
            u64 q2 = pack2(qv.z, qv.z), q3 = pack2(qv.w, qv.w);
            Sa[0][0] = ffma2(q0, kv.x, Sa[0][0]); Sa[0][1] = ffma2(q0, kv.y, Sa[0][1]);
            Sa[1][0] = ffma2(q1, kv.x, Sa[1][0]); Sa[1][1] = ffma2(q1, kv.y, Sa[1][1]);
            Sa[2][0] = ffma2(q2, kv.x, Sa[2][0]); Sa[2][1] = ffma2(q2, kv.y, Sa[2][1]);
            Sa[3][0] = ffma2(q3, kv.x, Sa[3][0]); Sa[3][1] = ffma2(q3, kv.y, Sa[3][1]);
        }

        // ---- online softmax over this key tile ----
        #pragma unroll
        for (int r = 0; r < 4; r++) {
            float2 s0 = unpack2(Sa[r][0]);
            float2 s1 = unpack2(Sa[r][1]);
            float rm = fmaxf(fmaxf(s0.x, s0.y), fmaxf(s1.x, s1.y));
            #pragma unroll
            for (int o = 8; o > 0; o >>= 1)
                rm = fmaxf(rm, __shfl_xor_sync(0xffffffffu, rm, o));
            float mn = fmaxf(m[r], rm);
            float sc = __expf(m[r] - mn);
            m[r] = mn;
            float p0 = __expf(s0.x - mn), p1 = __expf(s0.y - mn);
            float p2 = __expf(s1.x - mn), p3 = __expf(s1.y - mn);
            float rs = (p0 + p1) + (p2 + p3);
            #pragma unroll
            for (int o = 8; o > 0; o >>= 1)
                rs += __shfl_xor_sync(0xffffffffu, rs, o);
            l[r] = l[r] * sc + rs;
            u64 sc2 = pack2(sc, sc);
            #pragma unroll
            for (int pp = 0; pp < 4; pp++) {
                Oa[r][pp][0] = fmul2(Oa[r][pp][0], sc2);
                Oa[r][pp][1] = fmul2(Oa[r][pp][1], sc2);
            }
            Pt[(4 * tx + 0) * 68 + 4 * ty + r] = p0;
            Pt[(4 * tx + 1) * 68 + 4 * ty + r] = p1;
            Pt[(4 * tx + 2) * 68 + 4 * ty + r] = p2;
            Pt[(4 * tx + 3) * 68 + 4 * ty + r] = p3;
        }
        __syncthreads();

        // ---- O += P * V : thread tile i=4ty+r, c=64pp+4tx+(2h+e) ----
        #pragma unroll 2
        for (int j = 0; j < BK; j++) {
            float4 pv = *(float4*)&Pt[j * 68 + 4 * ty];
            u64 pr0 = pack2(pv.x, pv.x), pr1 = pack2(pv.y, pv.y);
            u64 pr2 = pack2(pv.z, pv.z), pr3 = pack2(pv.w, pv.w);
            #pragma unroll
            for (int pp = 0; pp < 4; pp++) {
                ulonglong2 vv = *(ulonglong2*)&Vt[j * 256 + 64 * pp + 4 * tx];
                Oa[0][pp][0] = ffma2(pr0, vv.x, Oa[0][pp][0]);
                Oa[0][pp][1] = ffma2(pr0, vv.y, Oa[0][pp][1]);
                Oa[1][pp][0] = ffma2(pr1, vv.x, Oa[1][pp][0]);
                Oa[1][pp][1] = ffma2(pr1, vv.y, Oa[1][pp][1]);
                Oa[2][pp][0] = ffma2(pr2, vv.x, Oa[2][pp][0]);
                Oa[2][pp][1] = ffma2(pr2, vv.y, Oa[2][pp][1]);
                Oa[3][pp][0] = ffma2(pr3, vv.x, Oa[3][pp][0]);
                Oa[3][pp][1] = ffma2(pr3, vv.y, Oa[3][pp][1]);
            }
        }
    }

    // ---- epilogue: O/l through smem transpose, + x, coalesced store ----
    __syncthreads();
    float* Os = sm;  // [64 i][257]
    #pragma unroll
    for (int r = 0; r < 4; r++) {
        float invl = 1.0f / l[r];
        int i = 4 * ty + r;
        #pragma unroll
        for (int pp = 0; pp < 4; pp++) {
            float2 a = unpack2(Oa[r][pp][0]);
            float2 c2 = unpack2(Oa[r][pp][1]);
            int cb = 64 * pp + 4 * tx;
            Os[i * 257 + cb + 0] = a.x * invl;
            Os[i * 257 + cb + 1] = a.y * invl;
            Os[i * 257 + cb + 2] = c2.x * invl;
            Os[i * 257 + cb + 3] = c2.y * invl;
        }
    }
    __syncthreads();

    const float* xb = x + (size_t)bb * CDIM * NSP;
    float* ob = out + (size_t)bb * CDIM * NSP;
    const int i = tid & 63;
    const int csub = tid >> 6;
    #pragma unroll 4
    for (int c0 = 0; c0 < CDIM; c0 += 4) {
        int c = c0 + csub;
        size_t g = (size_t)c * NSP + n0 + i;
        ob[g] = Os[i * 257 + c] + xb[g];
    }
}

// ---------------------------------------------------------------------------
extern "C" void kernel_launch(void* const* d_in, const int* in_sizes, int n_in,
                              void* d_out, int out_size)
{
    const float* x    = (const float*)d_in[0];
    const float* attr = (const float*)d_in[1];
    const float* Wq   = (const float*)d_in[2];
    const float* bq   = (const float*)d_in[3];
    const float* Wk   = (const float*)d_in[4];
    const float* bk   = (const float*)d_in[5];
    const float* Wv   = (const float*)d_in[6];
    const float* bv   = (const float*)d_in[7];
    float* out = (float*)d_out;

    cudaFuncSetAttribute(attn_kernel,
                         cudaFuncAttributeMaxDynamicSharedMemorySize, SM_BYTES);

    dim3 gp(NSP / 64, NB, 12);
    proj_kernel<<<gp, 256>>>(x, attr, Wq, bq, Wk, bk, Wv, bv);

    dim3 ga(NSP / BQ, NB);
    attn_kernel<<<ga, 256, SM_BYTES>>>(x, out);
}

// round 6
// speedup vs baseline: 3.0750x; 3.0750x over previous
#include <cuda_runtime.h>
#include <cuda_bf16.h>

#define NSP 4096
#define CDIM 256
#define NB 8
#define BQ 64
#define BK 64
#define NK (NSP / BK)

__device__ __align__(256) __nv_bfloat16 g_Qb1[(size_t)NB * NSP * CDIM];  // [b][n][c] hi
__device__ __align__(256) __nv_bfloat16 g_Qb2[(size_t)NB * NSP * CDIM];  // [b][n][c] lo
__device__ __align__(256) __nv_bfloat16 g_Kb1[(size_t)NB * NSP * CDIM];
__device__ __align__(256) __nv_bfloat16 g_Kb2[(size_t)NB * NSP * CDIM];
__device__ __align__(256) float         g_V  [(size_t)NB * CDIM * NSP]; // [b][c][n] tf32

typedef unsigned long long u64;
typedef unsigned int u32;

// ================= helpers =================
__device__ __forceinline__ u32 smem_u32(const void* p) {
    u32 a;
    asm("{ .reg .u64 t; cvta.to.shared.u64 t, %1; cvt.u32.u64 %0, t; }" : "=r"(a) : "l"(p));
    return a;
}
__device__ __forceinline__ float tf32r(float f) {
    float o; asm("cvt.rna.tf32.f32 %0, %1;" : "=f"(o) : "f"(f)); return o;
}
__device__ __forceinline__ void ldsm4(u32* r, u32 addr) {
    asm volatile("ldmatrix.sync.aligned.m8n8.x4.shared.b16 {%0,%1,%2,%3}, [%4];"
                 : "=r"(r[0]), "=r"(r[1]), "=r"(r[2]), "=r"(r[3]) : "r"(addr));
}
__device__ __forceinline__ void mma_bf16(float* d, const u32* a, u32 b0, u32 b1) {
    asm volatile(
        "mma.sync.aligned.m16n8k16.row.col.f32.bf16.bf16.f32 "
        "{%0,%1,%2,%3}, {%4,%5,%6,%7}, {%8,%9}, {%0,%1,%2,%3};"
        : "+f"(d[0]), "+f"(d[1]), "+f"(d[2]), "+f"(d[3])
        : "r"(a[0]), "r"(a[1]), "r"(a[2]), "r"(a[3]), "r"(b0), "r"(b1));
}
__device__ __forceinline__ void mma_tf32(float* d, u32 a0, u32 a1, u32 a2, u32 a3,
                                         u32 b0, u32 b1) {
    asm volatile(
        "mma.sync.aligned.m16n8k8.row.col.f32.tf32.tf32.f32 "
        "{%0,%1,%2,%3}, {%4,%5,%6,%7}, {%8,%9}, {%0,%1,%2,%3};"
        : "+f"(d[0]), "+f"(d[1]), "+f"(d[2]), "+f"(d[3])
        : "r"(a0), "r"(a1), "r"(a2), "r"(a3), "r"(b0), "r"(b1));
}
__device__ __forceinline__ u32 lds_u32(u32 a) {
    u32 v; asm volatile("ld.shared.b32 %0, [%1];" : "=r"(v) : "r"(a)); return v;
}
__device__ __forceinline__ float lds_f32(u32 a) {
    float v; asm volatile("ld.shared.f32 %0, [%1];" : "=f"(v) : "r"(a)); return v;
}
__device__ __forceinline__ void sts_v2f(u32 a, float x, float y) {
    asm volatile("st.shared.v2.f32 [%0], {%1,%2};" :: "r"(a), "f"(x), "f"(y) : "memory");
}
__device__ __forceinline__ void sts_v4(u32 a, uint4 v) {
    asm volatile("st.shared.v4.b32 [%0], {%1,%2,%3,%4};"
                 :: "r"(a), "r"(v.x), "r"(v.y), "r"(v.z), "r"(v.w) : "memory");
}
#define CP16(dst, src) asm volatile("cp.async.cg.shared.global [%0], [%1], 16;" \
    :: "r"(dst), "l"(src) : "memory")
#define CPCOMMIT() asm volatile("cp.async.commit_group;" ::: "memory")
#define CPWAIT(n)  asm volatile("cp.async.wait_group %0;" :: "n"(n) : "memory")

// ---- packed fp32 (proj) ----
__device__ __forceinline__ u64 ffma2(u64 a, u64 b, u64 c) {
    u64 d; asm("fma.rn.f32x2 %0, %1, %2, %3;" : "=l"(d) : "l"(a), "l"(b), "l"(c)); return d;
}
__device__ __forceinline__ u64 pack2(float lo, float hi) {
    u64 d; asm("mov.b64 %0, {%1, %2};" : "=l"(d) : "f"(lo), "f"(hi)); return d;
}
__device__ __forceinline__ float2 unpack2(u64 v) {
    float lo, hi; asm("mov.b64 {%0, %1}, %2;" : "=f"(lo), "=f"(hi) : "l"(v));
    return make_float2(lo, hi);
}

// ---------------------------------------------------------------------------
// Kernel 1: projections -> split-bf16 Q/K (transposed [b][n][c]) + tf32 V
// ---------------------------------------------------------------------------
__global__ __launch_bounds__(256) void proj_kernel(
    const float* __restrict__ x, const float* __restrict__ attr,
    const float* __restrict__ Wq, const float* __restrict__ bq,
    const float* __restrict__ Wk, const float* __restrict__ bk,
    const float* __restrict__ Wv, const float* __restrict__ bv)
{
    __shared__ __align__(16) float Xs[32 * 64];
    __shared__ __align__(16) float Wt[32 * 68];

    const int tid = threadIdx.x;
    const int tx = tid & 15, ty = tid >> 4;
    const int n0 = blockIdx.x * 64;
    const int bb = blockIdx.y;
    const int z = blockIdx.z;
    const int proj = z >> 2;
    const int o0 = (z & 3) * 64;

    const float* X; const float* W; const float* bias;
    if (proj == 0)      { X = x;    W = Wq; bias = bq; }
    else if (proj == 1) { X = attr; W = Wk; bias = bk; }
    else                { X = attr; W = Wv; bias = bv; }

    const float* Xb = X + (size_t)bb * CDIM * NSP;

    u64 acc[4][2];
    #pragma unroll
    for (int r = 0; r < 4; r++) {
        float b0 = bias[o0 + 4 * ty + r];
        acc[r][0] = pack2(b0, b0); acc[r][1] = acc[r][0];
    }

    for (int ck = 0; ck < 8; ck++) {
        const int c0 = ck * 32;
        __syncthreads();
        {
            int row = tid >> 3, col = (tid & 7) * 4;
            const float* src = Xb + (size_t)(c0 + row) * NSP + n0;
            *(float4*)&Xs[row * 64 + col]      = *(const float4*)&src[col];
            *(float4*)&Xs[row * 64 + col + 32] = *(const float4*)&src[col + 32];
        }
        {
            int oo = tid >> 2, cc0 = (tid & 3) * 8;
            const float* src = W + (size_t)(o0 + oo) * CDIM + c0 + cc0;
            float4 a = *(const float4*)&src[0];
            float4 c4 = *(const float4*)&src[4];
            Wt[(cc0 + 0) * 68 + oo] = a.x;  Wt[(cc0 + 1) * 68 + oo] = a.y;
            Wt[(cc0 + 2) * 68 + oo] = a.z;  Wt[(cc0 + 3) * 68 + oo] = a.w;
            Wt[(cc0 + 4) * 68 + oo] = c4.x; Wt[(cc0 + 5) * 68 + oo] = c4.y;
            Wt[(cc0 + 6) * 68 + oo] = c4.z; Wt[(cc0 + 7) * 68 + oo] = c4.w;
        }
        __syncthreads();

        #pragma unroll 8
        for (int cc = 0; cc < 32; cc++) {
            float4 wv = *(float4*)&Wt[cc * 68 + 4 * ty];
            ulonglong2 xv = *(ulonglong2*)&Xs[cc * 64 + 4 * tx];
            u64 w0 = pack2(wv.x, wv.x), w1 = pack2(wv.y, wv.y);
            u64 w2 = pack2(wv.z, wv.z), w3 = pack2(wv.w, wv.w);
            acc[0][0] = ffma2(w0, xv.x, acc[0][0]); acc[0][1] = ffma2(w0, xv.y, acc[0][1]);
            acc[1][0] = ffma2(w1, xv.x, acc[1][0]); acc[1][1] = ffma2(w1, xv.y, acc[1][1]);
            acc[2][0] = ffma2(w2, xv.x, acc[2][0]); acc[2][1] = ffma2(w2, xv.y, acc[2][1]);
            acc[3][0] = ffma2(w3, xv.x, acc[3][0]); acc[3][1] = ffma2(w3, xv.y, acc[3][1]);
        }
    }

    if (proj == 2) {
        #pragma unroll
        for (int r = 0; r < 4; r++) {
            float2 a = unpack2(acc[r][0]);
            float2 c2 = unpack2(acc[r][1]);
            float4 res = make_float4(tf32r(a.x), tf32r(a.y), tf32r(c2.x), tf32r(c2.y));
            *(float4*)&g_V[((size_t)bb * CDIM + o0 + 4 * ty + r) * NSP + n0 + 4 * tx] = res;
        }
    } else {
        __nv_bfloat16* d1 = (proj == 0) ? g_Qb1 : g_Kb1;
        __nv_bfloat16* d2 = (proj == 0) ? g_Qb2 : g_Kb2;
        #pragma unroll
        for (int nn = 0; nn < 4; nn++) {
            unsigned short hb[4], lb[4];
            #pragma unroll
            for (int r = 0; r < 4; r++) {
                float2 u = unpack2(acc[r][nn >> 1]);
                float f = (nn & 1) ? u.y : u.x;
                __nv_bfloat16 b1 = __float2bfloat16_rn(f);
                __nv_bfloat16 b2 = __float2bfloat16_rn(f - __bfloat162float(b1));
                hb[r] = __bfloat16_as_ushort(b1);
                lb[r] = __bfloat16_as_ushort(b2);
            }
            uint2 w1, w2;
            w1.x = (u32)hb[0] | ((u32)hb[1] << 16);
            w1.y = (u32)hb[2] | ((u32)hb[3] << 16);
            w2.x = (u32)lb[0] | ((u32)lb[1] << 16);
            w2.y = (u32)lb[2] | ((u32)lb[3] << 16);
            size_t base = ((size_t)bb * NSP + n0 + 4 * tx + nn) * CDIM + o0 + 4 * ty;
            *(uint2*)&d1[base] = w1;
            *(uint2*)&d2[base] = w2;
        }
    }
}

// ---------------------------------------------------------------------------
// Kernel 2: mma.sync flash attention (max-free softmax) + residual add.
// grid (64 qtiles, 8 b), 256 threads (8 warps: wr 0..3 x wc 0..1).
// ---------------------------------------------------------------------------
#define SQ1 0
#define SQ2 33792
#define SK1 67584
#define SK2 101376
#define SV  135168
#define SP  204800
#define SLR 222208
#define SM_TOTAL 222464
#define QK_STR 528
#define VP_STR 272
#define OT_STR 258   // floats (EVEN -> v2 stores 8B-aligned); Ot reuses SV region

__global__ __launch_bounds__(256, 1) void attn_kernel(
    const float* __restrict__ x, float* __restrict__ out)
{
    extern __shared__ __align__(16) char smem[];
    const u32 sb = smem_u32(smem);
    const int tid = threadIdx.x;
    const int lane = tid & 31;
    const int warp = tid >> 5;
    const int wr = warp >> 1, wc = warp & 1;
    const int gid = lane >> 2, tig = lane & 3;
    const int i0 = wr * 16;
    const int j0 = wc * 32;
    const int bb = blockIdx.y;
    const int n0 = blockIdx.x * BQ;

    float* lrow = (float*)(smem + SLR);
    if (tid < 64) lrow[tid] = 0.0f;

    const __nv_bfloat16* q1g = g_Qb1 + ((size_t)bb * NSP + n0) * CDIM;
    const __nv_bfloat16* q2g = g_Qb2 + ((size_t)bb * NSP + n0) * CDIM;
    const __nv_bfloat16* k1g = g_Kb1 + (size_t)bb * NSP * CDIM;
    const __nv_bfloat16* k2g = g_Kb2 + (size_t)bb * NSP * CDIM;
    const float*         vg  = g_V   + (size_t)bb * CDIM * NSP;

    // ---- load Q tiles (plain LDG -> STS) ----
    #pragma unroll
    for (int it = 0; it < 8; it++) {
        int idx = it * 256 + tid;
        int i = idx >> 5, ch = idx & 31;
        uint4 v1 = *(const uint4*)&q1g[(size_t)i * CDIM + ch * 8];
        uint4 v2 = *(const uint4*)&q2g[(size_t)i * CDIM + ch * 8];
        sts_v4(sb + SQ1 + i * QK_STR + ch * 16, v1);
        sts_v4(sb + SQ2 + i * QK_STR + ch * 16, v2);
    }

    // ---- cp.async issue helpers ----
    auto issueK = [&](int k0) {
        #pragma unroll
        for (int it = 0; it < 8; it++) {
            int idx = it * 256 + tid;
            int j = idx >> 5, ch = idx & 31;
            const __nv_bfloat16* s1 = &k1g[(size_t)(k0 + j) * CDIM + ch * 8];
            const __nv_bfloat16* s2 = &k2g[(size_t)(k0 + j) * CDIM + ch * 8];
            CP16(sb + SK1 + j * QK_STR + ch * 16, s1);
            CP16(sb + SK2 + j * QK_STR + ch * 16, s2);
        }
        CPCOMMIT();
    };
    auto issueV = [&](int k0) {
        #pragma unroll
        for (int it = 0; it < 16; it++) {
            int idx = it * 256 + tid;
            int c = idx >> 4, ch = idx & 15;
            const float* s = &vg[(size_t)c * NSP + k0 + ch * 4];
            CP16(sb + SV + c * VP_STR + ch * 16, s);
        }
        CPCOMMIT();
    };

    issueK(0);
    issueV(0);

    // ldmatrix base addresses
    const u32 aBase1 = sb + SQ1 + (i0 + (lane & 15)) * QK_STR + (lane >> 4) * 16;
    const u32 aBase2 = sb + SQ2 + (i0 + (lane & 15)) * QK_STR + (lane >> 4) * 16;
    const int bRow = j0 + (lane & 7) + ((lane >> 4) << 3);
    const u32 bOff = ((lane >> 3) & 1) * 16;
    const u32 bBase1 = sb + SK1 + bRow * QK_STR + bOff;
    const u32 bBase2 = sb + SK2 + bRow * QK_STR + bOff;

    float O[16][4];
    #pragma unroll
    for (int t = 0; t < 16; t++)
        #pragma unroll
        for (int e = 0; e < 4; e++) O[t][e] = 0.0f;
    float lsum0 = 0.0f, lsum1 = 0.0f;

    for (int kt = 0; kt < NK; kt++) {
        // K(kt) ready (leave V in flight)
        CPWAIT(1);
        __syncthreads();

        // ---- S = (q1+q2)(k1+k2)^T  (drop q2k2), bf16 mma ----
        float S[4][4];
        #pragma unroll
        for (int t = 0; t < 4; t++)
            #pragma unroll
            for (int e = 0; e < 4; e++) S[t][e] = 0.0f;

        #pragma unroll
        for (int kk = 0; kk < 16; kk++) {
            u32 aq1[4], aq2[4], bk1[8], bk2[8];
            ldsm4(aq1, aBase1 + kk * 32);
            ldsm4(aq2, aBase2 + kk * 32);
            ldsm4(bk1,     bBase1 + kk * 32);
            ldsm4(bk1 + 4, bBase1 + 16 * QK_STR + kk * 32);
            ldsm4(bk2,     bBase2 + kk * 32);
            ldsm4(bk2 + 4, bBase2 + 16 * QK_STR + kk * 32);
            #pragma unroll
            for (int t = 0; t < 4; t++) {
                mma_bf16(S[t], aq1, bk1[2 * t], bk1[2 * t + 1]);
                mma_bf16(S[t], aq1, bk2[2 * t], bk2[2 * t + 1]);
                mma_bf16(S[t], aq2, bk1[2 * t], bk1[2 * t + 1]);
            }
        }
        __syncthreads();                      // everyone done reading K
        issueK(((kt + 1) & (NK - 1)) * BK);   // prefetch next K (wraps harmlessly)

        // ---- P = exp(S) (max-free), store tf32 to smem ----
        #pragma unroll
        for (int t = 0; t < 4; t++) {
            int jc = j0 + 8 * t + 2 * tig;
            float p0 = __expf(S[t][0]), p1 = __expf(S[t][1]);
            float p2 = __expf(S[t][2]), p3 = __expf(S[t][3]);
            lsum0 += p0 + p1;
            lsum1 += p2 + p3;
            sts_v2f(sb + SP + ((i0 + gid) * 68 + jc) * 4, tf32r(p0), tf32r(p1));
            sts_v2f(sb + SP + ((i0 + gid + 8) * 68 + jc) * 4, tf32r(p2), tf32r(p3));
        }

        // V(kt) ready (K(kt+1) still in flight)
        CPWAIT(1);
        __syncthreads();

        // ---- O += P @ V^T, tf32 mma ----
        const u32 pB = sb + SP + ((i0 + gid) * 68 + tig) * 4;
        const u32 vB = sb + SV + ((wc * 128 + gid) * 68 + tig) * 4;
        #pragma unroll
        for (int ks = 0; ks < 8; ks++) {
            u32 pa = pB + ks * 32;
            u32 a0 = lds_u32(pa);
            u32 a1 = lds_u32(pa + 8 * VP_STR);
            u32 a2 = lds_u32(pa + 16);
            u32 a3 = lds_u32(pa + 8 * VP_STR + 16);
            #pragma unroll
            for (int t = 0; t < 16; t++) {
                u32 vb = vB + t * 8 * VP_STR + ks * 32;
                u32 b0 = lds_u32(vb);
                u32 b1 = lds_u32(vb + 16);
                mma_tf32(O[t], a0, a1, a2, a3, b0, b1);
            }
        }
        __syncthreads();                      // everyone done reading V and P
        if (kt + 1 < NK) issueV((kt + 1) * BK);
    }

    CPWAIT(0);

    // ---- per-row l: quad reduce + cross-warp atomic ----
    lsum0 += __shfl_xor_sync(0xffffffffu, lsum0, 1);
    lsum0 += __shfl_xor_sync(0xffffffffu, lsum0, 2);
    lsum1 += __shfl_xor_sync(0xffffffffu, lsum1, 1);
    lsum1 += __shfl_xor_sync(0xffffffffu, lsum1, 2);
    if (tig == 0) {
        atomicAdd(&lrow[i0 + gid], lsum0);
        atomicAdd(&lrow[i0 + gid + 8], lsum1);
    }
    __syncthreads();

    // ---- transpose O through smem (reuse V region) ----
    #pragma unroll
    for (int t = 0; t < 16; t++) {
        int c = wc * 128 + 8 * t + 2 * tig;
        sts_v2f(sb + SV + ((i0 + gid) * OT_STR + c) * 4, O[t][0], O[t][1]);
        sts_v2f(sb + SV + ((i0 + gid + 8) * OT_STR + c) * 4, O[t][2], O[t][3]);
    }
    __syncthreads();

    // ---- out = O/l + x, coalesced ----
    const float* xb = x + (size_t)bb * CDIM * NSP;
    float* ob = out + (size_t)bb * CDIM * NSP;
    const int i = tid & 63;
    const int cg = tid >> 6;
    const float invl = 1.0f / lrow[i];
    #pragma unroll 4
    for (int cc = 0; cc < 64; cc++) {
        int c = cc * 4 + cg;
        float ov = lds_f32(sb + SV + (i * OT_STR + c) * 4);
        size_t g = (size_t)c * NSP + n0 + i;
        ob[g] = ov * invl + xb[g];
    }
}

// ---------------------------------------------------------------------------
extern "C" void kernel_launch(void* const* d_in, const int* in_sizes, int n_in,
                              void* d_out, int out_size)
{
    const float* x    = (const float*)d_in[0];
    const float* attr = (const float*)d_in[1];
    const float* Wq   = (const float*)d_in[2];
    const float* bq   = (const float*)d_in[3];
    const float* Wk   = (const float*)d_in[4];
    const float* bk   = (const float*)d_in[5];
    const float* Wv   = (const float*)d_in[6];
    const float* bv   = (const float*)d_in[7];
    float* out = (float*)d_out;

    cudaFuncSetAttribute(attn_kernel,
                         cudaFuncAttributeMaxDynamicSharedMemorySize, SM_TOTAL);

    dim3 gp(NSP / 64, NB, 12);
    proj_kernel<<<gp, 256>>>(x, attr, Wq, bq, Wk, bk, Wv, bv);

    dim3 ga(NSP / BQ, NB);
    attn_kernel<<<ga, 256, SM_TOTAL>>>(x, out);
}

// round 7
// speedup vs baseline: 3.4619x; 1.1258x over previous
#include <cuda_runtime.h>
#include <cuda_bf16.h>

#define NSP 4096
#define CDIM 256
#define NB 8
#define BQ 64
#define BK 64
#define NK (NSP / BK)
#define LOG2E 1.4426950408889634f

// ---- scratch ----
__device__ __align__(256) __nv_bfloat16 g_Qb1[(size_t)NB * NSP * CDIM];  // [b][n][c] hi (xLOG2E)
__device__ __align__(256) __nv_bfloat16 g_Qb2[(size_t)NB * NSP * CDIM];  // [b][n][c] lo
__device__ __align__(256) __nv_bfloat16 g_Kb1[(size_t)NB * NSP * CDIM];
__device__ __align__(256) __nv_bfloat16 g_Kb2[(size_t)NB * NSP * CDIM];
__device__ __align__(256) float         g_V  [(size_t)NB * CDIM * NSP]; // [b][c][n] tf32
// split/transposed inputs [b][n][c]
__device__ __align__(256) __nv_bfloat16 g_Xx1[(size_t)NB * NSP * CDIM];
__device__ __align__(256) __nv_bfloat16 g_Xx2[(size_t)NB * NSP * CDIM];
__device__ __align__(256) __nv_bfloat16 g_Xa1[(size_t)NB * NSP * CDIM];
__device__ __align__(256) __nv_bfloat16 g_Xa2[(size_t)NB * NSP * CDIM];
// split weights [proj][o*256+c]
__device__ __align__(256) __nv_bfloat16 g_W1[3][65536];
__device__ __align__(256) __nv_bfloat16 g_W2[3][65536];

typedef unsigned long long u64;
typedef unsigned int u32;
typedef unsigned short u16;

// ================= helpers =================
__device__ __forceinline__ u32 smem_u32(const void* p) {
    u32 a;
    asm("{ .reg .u64 t; cvta.to.shared.u64 t, %1; cvt.u32.u64 %0, t; }" : "=r"(a) : "l"(p));
    return a;
}
__device__ __forceinline__ float tf32r(float f) {
    float o; asm("cvt.rna.tf32.f32 %0, %1;" : "=f"(o) : "f"(f)); return o;
}
__device__ __forceinline__ float ex2f(float x) {
    float y; asm("ex2.approx.f32 %0, %1;" : "=f"(y) : "f"(x)); return y;
}
__device__ __forceinline__ void ldsm4(u32* r, u32 addr) {
    asm volatile("ldmatrix.sync.aligned.m8n8.x4.shared.b16 {%0,%1,%2,%3}, [%4];"
                 : "=r"(r[0]), "=r"(r[1]), "=r"(r[2]), "=r"(r[3]) : "r"(addr));
}
__device__ __forceinline__ void mma_bf16(float* d, const u32* a, u32 b0, u32 b1) {
    asm volatile(
        "mma.sync.aligned.m16n8k16.row.col.f32.bf16.bf16.f32 "
        "{%0,%1,%2,%3}, {%4,%5,%6,%7}, {%8,%9}, {%0,%1,%2,%3};"
        : "+f"(d[0]), "+f"(d[1]), "+f"(d[2]), "+f"(d[3])
        : "r"(a[0]), "r"(a[1]), "r"(a[2]), "r"(a[3]), "r"(b0), "r"(b1));
}
__device__ __forceinline__ void mma_tf32(float* d, u32 a0, u32 a1, u32 a2, u32 a3,
                                         u32 b0, u32 b1) {
    asm volatile(
        "mma.sync.aligned.m16n8k8.row.col.f32.tf32.tf32.f32 "
        "{%0,%1,%2,%3}, {%4,%5,%6,%7}, {%8,%9}, {%0,%1,%2,%3};"
        : "+f"(d[0]), "+f"(d[1]), "+f"(d[2]), "+f"(d[3])
        : "r"(a0), "r"(a1), "r"(a2), "r"(a3), "r"(b0), "r"(b1));
}
__device__ __forceinline__ u32 lds_u32(u32 a) {
    u32 v; asm volatile("ld.shared.b32 %0, [%1];" : "=r"(v) : "r"(a)); return v;
}
__device__ __forceinline__ float lds_f32(u32 a) {
    float v; asm volatile("ld.shared.f32 %0, [%1];" : "=f"(v) : "r"(a)); return v;
}
__device__ __forceinline__ void sts_v2f(u32 a, float x, float y) {
    asm volatile("st.shared.v2.f32 [%0], {%1,%2};" :: "r"(a), "f"(x), "f"(y) : "memory");
}
__device__ __forceinline__ void sts_v4(u32 a, uint4 v) {
    asm volatile("st.shared.v4.b32 [%0], {%1,%2,%3,%4};"
                 :: "r"(a), "r"(v.x), "r"(v.y), "r"(v.z), "r"(v.w) : "memory");
}
#define CP16(dst, src) asm volatile("cp.async.cg.shared.global [%0], [%1], 16;" \
    :: "r"(dst), "l"(src) : "memory")
#define CPCOMMIT() asm volatile("cp.async.commit_group;" ::: "memory")
#define CPWAIT(n)  asm volatile("cp.async.wait_group %0;" :: "n"(n) : "memory")

__device__ __forceinline__ void bfsplit(float f, u16& hi, u16& lo) {
    __nv_bfloat16 h = __float2bfloat16_rn(f);
    __nv_bfloat16 l = __float2bfloat16_rn(f - __bfloat162float(h));
    hi = __bfloat16_as_ushort(h);
    lo = __bfloat16_as_ushort(l);
}

// ---------------------------------------------------------------------------
// Kernel A: split weights into bf16 hi/lo pairs.  grid 768 x 256 threads.
// ---------------------------------------------------------------------------
__global__ __launch_bounds__(256) void split_w(
    const float* __restrict__ Wq, const float* __restrict__ Wk,
    const float* __restrict__ Wv)
{
    int idx = blockIdx.x * 256 + threadIdx.x;           // 0 .. 196607
    int which = idx >> 16;
    int i = idx & 65535;
    const float* W = (which == 0) ? Wq : (which == 1) ? Wk : Wv;
    u16 h, l;
    bfsplit(W[i], h, l);
    g_W1[which][i] = __ushort_as_bfloat16(h);
    g_W2[which][i] = __ushort_as_bfloat16(l);
}

// ---------------------------------------------------------------------------
// Kernel B: split + transpose x/attr -> [b][n][c] bf16 hi/lo.
// grid (128 ntile, 8 ctile, 16 = b*2), 256 threads.
// ---------------------------------------------------------------------------
__global__ __launch_bounds__(256) void split_x(
    const float* __restrict__ x, const float* __restrict__ attr)
{
    __shared__ float t[32][33];
    const int tid = threadIdx.x;
    const int b = blockIdx.z >> 1, ten = blockIdx.z & 1;
    const float* src = ten ? attr : x;
    __nv_bfloat16* d1 = ten ? g_Xa1 : g_Xx1;
    __nv_bfloat16* d2 = ten ? g_Xa2 : g_Xx2;
    const int n0 = blockIdx.x * 32, c0 = blockIdx.y * 32;

    {
        int r = tid >> 3, n4 = (tid & 7) * 4;
        float4 v = *(const float4*)(src + ((size_t)b * CDIM + c0 + r) * NSP + n0 + n4);
        t[r][n4 + 0] = v.x; t[r][n4 + 1] = v.y;
        t[r][n4 + 2] = v.z; t[r][n4 + 3] = v.w;
    }
    __syncthreads();
    {
        int nr = tid >> 3, c4 = (tid & 7) * 4;
        u16 h[4], l[4];
        #pragma unroll
        for (int k = 0; k < 4; k++) bfsplit(t[c4 + k][nr], h[k], l[k]);
        uint2 hw, lw;
        hw.x = (u32)h[0] | ((u32)h[1] << 16); hw.y = (u32)h[2] | ((u32)h[3] << 16);
        lw.x = (u32)l[0] | ((u32)l[1] << 16); lw.y = (u32)l[2] | ((u32)l[3] << 16);
        size_t base = ((size_t)b * NSP + n0 + nr) * CDIM + c0 + c4;
        *(uint2*)&d1[base] = hw;
        *(uint2*)&d2[base] = lw;
    }
}

// ---------------------------------------------------------------------------
// Kernel C: proj via mma (3-pass split bf16).  grid (64 ntile, 8 b, 3 proj).
// Q epilogue also folds LOG2E.  V epilogue: tf32 round + transpose to [c][n].
// ---------------------------------------------------------------------------
#define PJ_X1 0
#define PJ_X2 33792
#define PJ_W  67584            // 2 bufs x 67584 (w1 at +0, w2 at +33792)
#define PJ_ST 202752           // 64 x 68 floats staging (V transpose)
#define PJ_B  220160           // 256 bias floats
#define PJ_TOTAL 221184

__global__ __launch_bounds__(256, 1) void proj_mma(
    const float* __restrict__ bq, const float* __restrict__ bk,
    const float* __restrict__ bv)
{
    extern __shared__ __align__(16) char smem[];
    const u32 sb = smem_u32(smem);
    const int tid = threadIdx.x;
    const int lane = tid & 31, warp = tid >> 5;
    const int wr = warp >> 1, wc = warp & 1;
    const int gid = lane >> 2, tig = lane & 3;
    const int z = blockIdx.z, bb = blockIdx.y, n0 = blockIdx.x * 64;

    const __nv_bfloat16* xs1 = (z == 0) ? g_Xx1 : g_Xa1;
    const __nv_bfloat16* xs2 = (z == 0) ? g_Xx2 : g_Xa2;
    const __nv_bfloat16* w1 = g_W1[z];
    const __nv_bfloat16* w2 = g_W2[z];
    const float* bias = (z == 0) ? bq : (z == 1) ? bk : bv;

    float* bias_s = (float*)(smem + PJ_B);
    bias_s[tid] = bias[tid];

    // X tile (64 n x 256 c, both splits) via cp.async
    #pragma unroll
    for (int it = 0; it < 8; it++) {
        int idx = it * 256 + tid;
        int j = idx >> 5, ch = idx & 31;
        size_t off = ((size_t)bb * NSP + n0 + j) * CDIM + ch * 8;
        CP16(sb + PJ_X1 + j * 528 + ch * 16, xs1 + off);
        CP16(sb + PJ_X2 + j * 528 + ch * 16, xs2 + off);
    }
    CPCOMMIT();

    auto issueW = [&](int oq) {
        u32 base = sb + PJ_W + (oq & 1) * 67584;
        #pragma unroll
        for (int it = 0; it < 8; it++) {
            int idx = it * 256 + tid;
            int o = idx >> 5, ch = idx & 31;
            size_t off = (size_t)(oq * 64 + o) * CDIM + ch * 8;
            CP16(base + o * 528 + ch * 16, w1 + off);
            CP16(base + 33792 + o * 528 + ch * 16, w2 + off);
        }
        CPCOMMIT();
    };
    issueW(0);

    const u32 aB1 = sb + PJ_X1 + (wr * 16 + (lane & 15)) * 528 + (lane >> 4) * 16;
    const u32 aB2 = sb + PJ_X2 + (wr * 16 + (lane & 15)) * 528 + (lane >> 4) * 16;
    const int bRow = wc * 32 + (lane & 7) + ((lane >> 4) << 3);
    const u32 bOffc = ((lane >> 3) & 1) * 16;

    for (int oq = 0; oq < 4; oq++) {
        CPWAIT(0);
        __syncthreads();
        if (oq < 3) issueW(oq + 1);

        u32 wbase = sb + PJ_W + (oq & 1) * 67584;
        u32 bB1 = wbase + bRow * 528 + bOffc;
        u32 bB2 = bB1 + 33792;

        float D[4][4];
        #pragma unroll
        for (int t = 0; t < 4; t++)
            #pragma unroll
            for (int e = 0; e < 4; e++) D[t][e] = 0.0f;

        #pragma unroll
        for (int kk = 0; kk < 16; kk++) {
            u32 a1[4], a2[4], bw1[8], bw2[8];
            ldsm4(a1, aB1 + kk * 32);
            ldsm4(a2, aB2 + kk * 32);
            ldsm4(bw1,     bB1 + kk * 32);
            ldsm4(bw1 + 4, bB1 + 16 * 528 + kk * 32);
            ldsm4(bw2,     bB2 + kk * 32);
            ldsm4(bw2 + 4, bB2 + 16 * 528 + kk * 32);
            #pragma unroll
            for (int t = 0; t < 4; t++) {
                mma_bf16(D[t], a1, bw1[2 * t], bw1[2 * t + 1]);
                mma_bf16(D[t], a1, bw2[2 * t], bw2[2 * t + 1]);
                mma_bf16(D[t], a2, bw1[2 * t], bw1[2 * t + 1]);
            }
        }

        if (z < 2) {
            __nv_bfloat16* d1 = (z == 0) ? g_Qb1 : g_Kb1;
            __nv_bfloat16* d2 = (z == 0) ? g_Qb2 : g_Kb2;
            const float sc = (z == 0) ? LOG2E : 1.0f;
            #pragma unroll
            for (int t = 0; t < 4; t++) {
                int o = oq * 64 + wc * 32 + t * 8 + 2 * tig;
                float b0 = bias_s[o], b1 = bias_s[o + 1];
                #pragma unroll
                for (int rh = 0; rh < 2; rh++) {
                    float f0 = (D[t][2 * rh + 0] + b0) * sc;
                    float f1 = (D[t][2 * rh + 1] + b1) * sc;
                    u16 h0, l0, h1, l1;
                    bfsplit(f0, h0, l0);
                    bfsplit(f1, h1, l1);
                    int n = n0 + wr * 16 + gid + rh * 8;
                    size_t idx = ((size_t)bb * NSP + n) * CDIM + o;
                    *(u32*)&d1[idx] = (u32)h0 | ((u32)h1 << 16);
                    *(u32*)&d2[idx] = (u32)l0 | ((u32)l1 << 16);
                }
            }
        } else {
            float* st = (float*)(smem + PJ_ST);
            #pragma unroll
            for (int t = 0; t < 4; t++) {
                int ol = wc * 32 + t * 8 + 2 * tig;
                float b0 = bias_s[oq * 64 + ol], b1 = bias_s[oq * 64 + ol + 1];
                #pragma unroll
                for (int rh = 0; rh < 2; rh++) {
                    int nl = wr * 16 + gid + rh * 8;
                    st[ol * 68 + nl]       = D[t][2 * rh + 0] + b0;
                    st[(ol + 1) * 68 + nl] = D[t][2 * rh + 1] + b1;
                }
            }
            __syncthreads();
            int ol = tid >> 2, nch = (tid & 3) * 16;
            float* dst = g_V + ((size_t)bb * CDIM + oq * 64 + ol) * NSP + n0 + nch;
            #pragma unroll
            for (int k = 0; k < 4; k++) {
                float4 v;
                v.x = tf32r(st[ol * 68 + nch + 4 * k + 0]);
                v.y = tf32r(st[ol * 68 + nch + 4 * k + 1]);
                v.z = tf32r(st[ol * 68 + nch + 4 * k + 2]);
                v.w = tf32r(st[ol * 68 + nch + 4 * k + 3]);
                *(float4*)(dst + 4 * k) = v;
            }
        }
    }
}

// ---------------------------------------------------------------------------
// Kernel D: mma.sync flash attention (max-free softmax, exp2) + residual.
// grid (64 qtiles, 8 b), 256 threads (8 warps: wr 0..3 x wc 0..1).
// ---------------------------------------------------------------------------
#define SQ1 0
#define SQ2 33792
#define SK1 67584
#define SK2 101376
#define SV  135168
#define SP  204800
#define SLR 222208
#define SM_TOTAL 222464
#define QK_STR 528
#define VP_STR 272
#define OT_STR 258

__global__ __launch_bounds__(256, 1) void attn_kernel(
    const float* __restrict__ x, float* __restrict__ out)
{
    extern __shared__ __align__(16) char smem[];
    const u32 sb = smem_u32(smem);
    const int tid = threadIdx.x;
    const int lane = tid & 31;
    const int warp = tid >> 5;
    const int wr = warp >> 1, wc = warp & 1;
    const int gid = lane >> 2, tig = lane & 3;
    const int i0 = wr * 16;
    const int j0 = wc * 32;
    const int bb = blockIdx.y;
    const int n0 = blockIdx.x * BQ;

    float* lrow = (float*)(smem + SLR);
    if (tid < 64) lrow[tid] = 0.0f;

    const __nv_bfloat16* q1g = g_Qb1 + ((size_t)bb * NSP + n0) * CDIM;
    const __nv_bfloat16* q2g = g_Qb2 + ((size_t)bb * NSP + n0) * CDIM;
    const __nv_bfloat16* k1g = g_Kb1 + (size_t)bb * NSP * CDIM;
    const __nv_bfloat16* k2g = g_Kb2 + (size_t)bb * NSP * CDIM;
    const float*         vg  = g_V   + (size_t)bb * CDIM * NSP;

    #pragma unroll
    for (int it = 0; it < 8; it++) {
        int idx = it * 256 + tid;
        int i = idx >> 5, ch = idx & 31;
        uint4 v1 = *(const uint4*)&q1g[(size_t)i * CDIM + ch * 8];
        uint4 v2 = *(const uint4*)&q2g[(size_t)i * CDIM + ch * 8];
        sts_v4(sb + SQ1 + i * QK_STR + ch * 16, v1);
        sts_v4(sb + SQ2 + i * QK_STR + ch * 16, v2);
    }

    auto issueK = [&](int k0) {
        #pragma unroll
        for (int it = 0; it < 8; it++) {
            int idx = it * 256 + tid;
            int j = idx >> 5, ch = idx & 31;
            const __nv_bfloat16* s1 = &k1g[(size_t)(k0 + j) * CDIM + ch * 8];
            const __nv_bfloat16* s2 = &k2g[(size_t)(k0 + j) * CDIM + ch * 8];
            CP16(sb + SK1 + j * QK_STR + ch * 16, s1);
            CP16(sb + SK2 + j * QK_STR + ch * 16, s2);
        }
        CPCOMMIT();
    };
    auto issueV = [&](int k0) {
        #pragma unroll
        for (int it = 0; it < 16; it++) {
            int idx = it * 256 + tid;
            int c = idx >> 4, ch = idx & 15;
            const float* s = &vg[(size_t)c * NSP + k0 + ch * 4];
            CP16(sb + SV + c * VP_STR + ch * 16, s);
        }
        CPCOMMIT();
    };

    issueK(0);
    issueV(0);

    const u32 aBase1 = sb + SQ1 + (i0 + (lane & 15)) * QK_STR + (lane >> 4) * 16;
    const u32 aBase2 = sb + SQ2 + (i0 + (lane & 15)) * QK_STR + (lane >> 4) * 16;
    const int bRow = j0 + (lane & 7) + ((lane >> 4) << 3);
    const u32 bOff = ((lane >> 3) & 1) * 16;
    const u32 bBase1 = sb + SK1 + bRow * QK_STR + bOff;
    const u32 bBase2 = sb + SK2 + bRow * QK_STR + bOff;

    float O[16][4];
    #pragma unroll
    for (int t = 0; t < 16; t++)
        #pragma unroll
        for (int e = 0; e < 4; e++) O[t][e] = 0.0f;
    float lsum0 = 0.0f, lsum1 = 0.0f;

    for (int kt = 0; kt < NK; kt++) {
        CPWAIT(1);
        __syncthreads();

        float S[4][4];
        #pragma unroll
        for (int t = 0; t < 4; t++)
            #pragma unroll
            for (int e = 0; e < 4; e++) S[t][e] = 0.0f;

        #pragma unroll
        for (int kk = 0; kk < 16; kk++) {
            u32 aq1[4], aq2[4], bk1[8], bk2[8];
            ldsm4(aq1, aBase1 + kk * 32);
            ldsm4(aq2, aBase2 + kk * 32);
            ldsm4(bk1,     bBase1 + kk * 32);
            ldsm4(bk1 + 4, bBase1 + 16 * QK_STR + kk * 32);
            ldsm4(bk2,     bBase2 + kk * 32);
            ldsm4(bk2 + 4, bBase2 + 16 * QK_STR + kk * 32);
            #pragma unroll
            for (int t = 0; t < 4; t++) {
                mma_bf16(S[t], aq1, bk1[2 * t], bk1[2 * t + 1]);
                mma_bf16(S[t], aq1, bk2[2 * t], bk2[2 * t + 1]);
                mma_bf16(S[t], aq2, bk1[2 * t], bk1[2 * t + 1]);
            }
        }
        __syncthreads();
        issueK(((kt + 1) & (NK - 1)) * BK);

        #pragma unroll
        for (int t = 0; t < 4; t++) {
            int jc = j0 + 8 * t + 2 * tig;
            float p0 = ex2f(S[t][0]), p1 = ex2f(S[t][1]);
            float p2 = ex2f(S[t][2]), p3 = ex2f(S[t][3]);
            lsum0 += p0 + p1;
            lsum1 += p2 + p3;
            sts_v2f(sb + SP + ((i0 + gid) * 68 + jc) * 4, tf32r(p0), tf32r(p1));
            sts_v2f(sb + SP + ((i0 + gid + 8) * 68 + jc) * 4, tf32r(p2), tf32r(p3));
        }

        CPWAIT(1);
        __syncthreads();

        const u32 pB = sb + SP + ((i0 + gid) * 68 + tig) * 4;
        const u32 vB = sb + SV + ((wc * 128 + gid) * 68 + tig) * 4;
        #pragma unroll
        for (int ks = 0; ks < 8; ks++) {
            u32 pa = pB + ks * 32;
            u32 a0 = lds_u32(pa);
            u32 a1 = lds_u32(pa + 8 * VP_STR);
            u32 a2 = lds_u32(pa + 16);
            u32 a3 = lds_u32(pa + 8 * VP_STR + 16);
            #pragma unroll
            for (int t = 0; t < 16; t++) {
                u32 vb = vB + t * 8 * VP_STR + ks * 32;
                u32 b0 = lds_u32(vb);
                u32 b1 = lds_u32(vb + 16);
                mma_tf32(O[t], a0, a1, a2, a3, b0, b1);
            }
        }
        __syncthreads();
        if (kt + 1 < NK) issueV((kt + 1) * BK);
    }

    CPWAIT(0);

    lsum0 += __shfl_xor_sync(0xffffffffu, lsum0, 1);
    lsum0 += __shfl_xor_sync(0xffffffffu, lsum0, 2);
    lsum1 += __shfl_xor_sync(0xffffffffu, lsum1, 1);
    lsum1 += __shfl_xor_sync(0xffffffffu, lsum1, 2);
    if (tig == 0) {
        atomicAdd(&lrow[i0 + gid], lsum0);
        atomicAdd(&lrow[i0 + gid + 8], lsum1);
    }
    __syncthreads();

    #pragma unroll
    for (int t = 0; t < 16; t++) {
        int c = wc * 128 + 8 * t + 2 * tig;
        sts_v2f(sb + SV + ((i0 + gid) * OT_STR + c) * 4, O[t][0], O[t][1]);
        sts_v2f(sb + SV + ((i0 + gid + 8) * OT_STR + c) * 4, O[t][2], O[t][3]);
    }
    __syncthreads();

    const float* xb = x + (size_t)bb * CDIM * NSP;
    float* ob = out + (size_t)bb * CDIM * NSP;
    const int i = tid & 63;
    const int cg = tid >> 6;
    const float invl = 1.0f / lrow[i];
    #pragma unroll 4
    for (int cc = 0; cc < 64; cc++) {
        int c = cc * 4 + cg;
        float ov = lds_f32(sb + SV + (i * OT_STR + c) * 4);
        size_t g = (size_t)c * NSP + n0 + i;
        ob[g] = ov * invl + xb[g];
    }
}

// ---------------------------------------------------------------------------
extern "C" void kernel_launch(void* const* d_in, const int* in_sizes, int n_in,
                              void* d_out, int out_size)
{
    const float* x    = (const float*)d_in[0];
    const float* attr = (const float*)d_in[1];
    const float* Wq   = (const float*)d_in[2];
    const float* bq   = (const float*)d_in[3];
    const float* Wk   = (const float*)d_in[4];
    const float* bk   = (const float*)d_in[5];
    const float* Wv   = (const float*)d_in[6];
    const float* bv   = (const float*)d_in[7];
    float* out = (float*)d_out;

    cudaFuncSetAttribute(proj_mma,
                         cudaFuncAttributeMaxDynamicSharedMemorySize, PJ_TOTAL);
    cudaFuncSetAttribute(attn_kernel,
                         cudaFuncAttributeMaxDynamicSharedMemorySize, SM_TOTAL);

    split_w<<<768, 256>>>(Wq, Wk, Wv);
    split_x<<<dim3(NSP / 32, CDIM / 32, NB * 2), 256>>>(x, attr);
    proj_mma<<<dim3(NSP / 64, NB, 3), 256, PJ_TOTAL>>>(bq, bk, bv);
    attn_kernel<<<dim3(NSP / BQ, NB), 256, SM_TOTAL>>>(x, out);
}

// round 8
// speedup vs baseline: 4.2143x; 1.2173x over previous
#include <cuda_runtime.h>
#include <cuda_bf16.h>
#include <cuda_fp16.h>

#define NSP 4096
#define CDIM 256
#define NB 8
#define BQ 64
#define BK 64
#define NK (NSP / BK)
#define LOG2E 1.4426950408889634f

// ---- scratch ----
__device__ __align__(256) __half g_Qh1[(size_t)NB * NSP * CDIM];  // [b][n][c] hi (xLOG2E)
__device__ __align__(256) __half g_Qh2[(size_t)NB * NSP * CDIM];  // [b][n][c] lo
__device__ __align__(256) __half g_Kh [(size_t)NB * NSP * CDIM];  // [b][n][c] fp16
__device__ __align__(256) float  g_V  [(size_t)NB * CDIM * NSP];  // [b][c][n] tf32
// split/transposed inputs [b][n][c] (bf16 pairs, proj GEMM operands)
__device__ __align__(256) __nv_bfloat16 g_Xx1[(size_t)NB * NSP * CDIM];
__device__ __align__(256) __nv_bfloat16 g_Xx2[(size_t)NB * NSP * CDIM];
__device__ __align__(256) __nv_bfloat16 g_Xa1[(size_t)NB * NSP * CDIM];
__device__ __align__(256) __nv_bfloat16 g_Xa2[(size_t)NB * NSP * CDIM];
// split weights [proj][o*256+c]
__device__ __align__(256) __nv_bfloat16 g_W1[3][65536];
__device__ __align__(256) __nv_bfloat16 g_W2[3][65536];

typedef unsigned long long u64;
typedef unsigned int u32;
typedef unsigned short u16;

// ================= helpers =================
__device__ __forceinline__ u32 smem_u32(const void* p) {
    u32 a;
    asm("{ .reg .u64 t; cvta.to.shared.u64 t, %1; cvt.u32.u64 %0, t; }" : "=r"(a) : "l"(p));
    return a;
}
__device__ __forceinline__ float tf32r(float f) {
    float o; asm("cvt.rna.tf32.f32 %0, %1;" : "=f"(o) : "f"(f)); return o;
}
__device__ __forceinline__ float ex2f(float x) {
    float y; asm("ex2.approx.f32 %0, %1;" : "=f"(y) : "f"(x)); return y;
}
__device__ __forceinline__ void ldsm4(u32* r, u32 addr) {
    asm volatile("ldmatrix.sync.aligned.m8n8.x4.shared.b16 {%0,%1,%2,%3}, [%4];"
                 : "=r"(r[0]), "=r"(r[1]), "=r"(r[2]), "=r"(r[3]) : "r"(addr));
}
__device__ __forceinline__ void mma_bf16(float* d, const u32* a, u32 b0, u32 b1) {
    asm volatile(
        "mma.sync.aligned.m16n8k16.row.col.f32.bf16.bf16.f32 "
        "{%0,%1,%2,%3}, {%4,%5,%6,%7}, {%8,%9}, {%0,%1,%2,%3};"
        : "+f"(d[0]), "+f"(d[1]), "+f"(d[2]), "+f"(d[3])
        : "r"(a[0]), "r"(a[1]), "r"(a[2]), "r"(a[3]), "r"(b0), "r"(b1));
}
__device__ __forceinline__ void mma_f16(float* d, const u32* a, u32 b0, u32 b1) {
    asm volatile(
        "mma.sync.aligned.m16n8k16.row.col.f32.f16.f16.f32 "
        "{%0,%1,%2,%3}, {%4,%5,%6,%7}, {%8,%9}, {%0,%1,%2,%3};"
        : "+f"(d[0]), "+f"(d[1]), "+f"(d[2]), "+f"(d[3])
        : "r"(a[0]), "r"(a[1]), "r"(a[2]), "r"(a[3]), "r"(b0), "r"(b1));
}
__device__ __forceinline__ void mma_tf32(float* d, u32 a0, u32 a1, u32 a2, u32 a3,
                                         u32 b0, u32 b1) {
    asm volatile(
        "mma.sync.aligned.m16n8k8.row.col.f32.tf32.tf32.f32 "
        "{%0,%1,%2,%3}, {%4,%5,%6,%7}, {%8,%9}, {%0,%1,%2,%3};"
        : "+f"(d[0]), "+f"(d[1]), "+f"(d[2]), "+f"(d[3])
        : "r"(a0), "r"(a1), "r"(a2), "r"(a3), "r"(b0), "r"(b1));
}
__device__ __forceinline__ u32 lds_u32(u32 a) {
    u32 v; asm volatile("ld.shared.b32 %0, [%1];" : "=r"(v) : "r"(a)); return v;
}
__device__ __forceinline__ float lds_f32(u32 a) {
    float v; asm volatile("ld.shared.f32 %0, [%1];" : "=f"(v) : "r"(a)); return v;
}
__device__ __forceinline__ void sts_v2f(u32 a, float x, float y) {
    asm volatile("st.shared.v2.f32 [%0], {%1,%2};" :: "r"(a), "f"(x), "f"(y) : "memory");
}
__device__ __forceinline__ void sts_v4(u32 a, uint4 v) {
    asm volatile("st.shared.v4.b32 [%0], {%1,%2,%3,%4};"
                 :: "r"(a), "r"(v.x), "r"(v.y), "r"(v.z), "r"(v.w) : "memory");
}
#define CP16(dst, src) asm volatile("cp.async.cg.shared.global [%0], [%1], 16;" \
    :: "r"(dst), "l"(src) : "memory")
#define CPCOMMIT() asm volatile("cp.async.commit_group;" ::: "memory")
#define CPWAIT(n)  asm volatile("cp.async.wait_group %0;" :: "n"(n) : "memory")
#define BAR_PAIR(id) asm volatile("bar.sync %0, %1;" :: "r"(id), "r"(64) : "memory")

__device__ __forceinline__ void bfsplit(float f, u16& hi, u16& lo) {
    __nv_bfloat16 h = __float2bfloat16_rn(f);
    __nv_bfloat16 l = __float2bfloat16_rn(f - __bfloat162float(h));
    hi = __bfloat16_as_ushort(h);
    lo = __bfloat16_as_ushort(l);
}

// ---------------------------------------------------------------------------
// Kernel A: split weights into bf16 hi/lo pairs.
// ---------------------------------------------------------------------------
__global__ __launch_bounds__(256) void split_w(
    const float* __restrict__ Wq, const float* __restrict__ Wk,
    const float* __restrict__ Wv)
{
    int idx = blockIdx.x * 256 + threadIdx.x;
    int which = idx >> 16;
    int i = idx & 65535;
    const float* W = (which == 0) ? Wq : (which == 1) ? Wk : Wv;
    u16 h, l;
    bfsplit(W[i], h, l);
    g_W1[which][i] = __ushort_as_bfloat16(h);
    g_W2[which][i] = __ushort_as_bfloat16(l);
}

// ---------------------------------------------------------------------------
// Kernel B: split + transpose x/attr -> [b][n][c] bf16 hi/lo.
// ---------------------------------------------------------------------------
__global__ __launch_bounds__(256) void split_x(
    const float* __restrict__ x, const float* __restrict__ attr)
{
    __shared__ float t[32][33];
    const int tid = threadIdx.x;
    const int b = blockIdx.z >> 1, ten = blockIdx.z & 1;
    const float* src = ten ? attr : x;
    __nv_bfloat16* d1 = ten ? g_Xa1 : g_Xx1;
    __nv_bfloat16* d2 = ten ? g_Xa2 : g_Xx2;
    const int n0 = blockIdx.x * 32, c0 = blockIdx.y * 32;

    {
        int r = tid >> 3, n4 = (tid & 7) * 4;
        float4 v = *(const float4*)(src + ((size_t)b * CDIM + c0 + r) * NSP + n0 + n4);
        t[r][n4 + 0] = v.x; t[r][n4 + 1] = v.y;
        t[r][n4 + 2] = v.z; t[r][n4 + 3] = v.w;
    }
    __syncthreads();
    {
        int nr = tid >> 3, c4 = (tid & 7) * 4;
        u16 h[4], l[4];
        #pragma unroll
        for (int k = 0; k < 4; k++) bfsplit(t[c4 + k][nr], h[k], l[k]);
        uint2 hw, lw;
        hw.x = (u32)h[0] | ((u32)h[1] << 16); hw.y = (u32)h[2] | ((u32)h[3] << 16);
        lw.x = (u32)l[0] | ((u32)l[1] << 16); lw.y = (u32)l[2] | ((u32)l[3] << 16);
        size_t base = ((size_t)b * NSP + n0 + nr) * CDIM + c0 + c4;
        *(uint2*)&d1[base] = hw;
        *(uint2*)&d2[base] = lw;
    }
}

// ---------------------------------------------------------------------------
// Kernel C: proj via mma (3-pass split bf16 core).
// Q epilogue: fp16 split, LOG2E folded.  K: single fp16.  V: tf32 [c][n].
// ---------------------------------------------------------------------------
#define PJ_X1 0
#define PJ_X2 33792
#define PJ_W  67584
#define PJ_ST 202752
#define PJ_B  220160
#define PJ_TOTAL 221184

__global__ __launch_bounds__(256, 1) void proj_mma(
    const float* __restrict__ bq, const float* __restrict__ bk,
    const float* __restrict__ bv)
{
    extern __shared__ __align__(16) char smem[];
    const u32 sb = smem_u32(smem);
    const int tid = threadIdx.x;
    const int lane = tid & 31, warp = tid >> 5;
    const int wr = warp >> 1, wc = warp & 1;
    const int gid = lane >> 2, tig = lane & 3;
    const int z = blockIdx.z, bb = blockIdx.y, n0 = blockIdx.x * 64;

    const __nv_bfloat16* xs1 = (z == 0) ? g_Xx1 : g_Xa1;
    const __nv_bfloat16* xs2 = (z == 0) ? g_Xx2 : g_Xa2;
    const __nv_bfloat16* w1 = g_W1[z];
    const __nv_bfloat16* w2 = g_W2[z];
    const float* bias = (z == 0) ? bq : (z == 1) ? bk : bv;

    float* bias_s = (float*)(smem + PJ_B);
    bias_s[tid] = bias[tid];

    #pragma unroll
    for (int it = 0; it < 8; it++) {
        int idx = it * 256 + tid;
        int j = idx >> 5, ch = idx & 31;
        size_t off = ((size_t)bb * NSP + n0 + j) * CDIM + ch * 8;
        CP16(sb + PJ_X1 + j * 528 + ch * 16, xs1 + off);
        CP16(sb + PJ_X2 + j * 528 + ch * 16, xs2 + off);
    }
    CPCOMMIT();

    auto issueW = [&](int oq) {
        u32 base = sb + PJ_W + (oq & 1) * 67584;
        #pragma unroll
        for (int it = 0; it < 8; it++) {
            int idx = it * 256 + tid;
            int o = idx >> 5, ch = idx & 31;
            size_t off = (size_t)(oq * 64 + o) * CDIM + ch * 8;
            CP16(base + o * 528 + ch * 16, w1 + off);
            CP16(base + 33792 + o * 528 + ch * 16, w2 + off);
        }
        CPCOMMIT();
    };
    issueW(0);

    const u32 aB1 = sb + PJ_X1 + (wr * 16 + (lane & 15)) * 528 + (lane >> 4) * 16;
    const u32 aB2 = sb + PJ_X2 + (wr * 16 + (lane & 15)) * 528 + (lane >> 4) * 16;
    const int bRow = wc * 32 + (lane & 7) + ((lane >> 4) << 3);
    const u32 bOffc = ((lane >> 3) & 1) * 16;

    for (int oq = 0; oq < 4; oq++) {
        CPWAIT(0);
        __syncthreads();
        if (oq < 3) issueW(oq + 1);

        u32 wbase = sb + PJ_W + (oq & 1) * 67584;
        u32 bB1 = wbase + bRow * 528 + bOffc;
        u32 bB2 = bB1 + 33792;

        float D[4][4];
        #pragma unroll
        for (int t = 0; t < 4; t++)
            #pragma unroll
            for (int e = 0; e < 4; e++) D[t][e] = 0.0f;

        #pragma unroll
        for (int kk = 0; kk < 16; kk++) {
            u32 a1[4], a2[4], bw1[8], bw2[8];
            ldsm4(a1, aB1 + kk * 32);
            ldsm4(a2, aB2 + kk * 32);
            ldsm4(bw1,     bB1 + kk * 32);
            ldsm4(bw1 + 4, bB1 + 16 * 528 + kk * 32);
            ldsm4(bw2,     bB2 + kk * 32);
            ldsm4(bw2 + 4, bB2 + 16 * 528 + kk * 32);
            #pragma unroll
            for (int t = 0; t < 4; t++) {
                mma_bf16(D[t], a1, bw1[2 * t], bw1[2 * t + 1]);
                mma_bf16(D[t], a1, bw2[2 * t], bw2[2 * t + 1]);
                mma_bf16(D[t], a2, bw1[2 * t], bw1[2 * t + 1]);
            }
        }

        if (z < 2) {
            #pragma unroll
            for (int t = 0; t < 4; t++) {
                int o = oq * 64 + wc * 32 + t * 8 + 2 * tig;
                float b0 = bias_s[o], b1 = bias_s[o + 1];
                #pragma unroll
                for (int rh = 0; rh < 2; rh++) {
                    float f0 = D[t][2 * rh + 0] + b0;
                    float f1 = D[t][2 * rh + 1] + b1;
                    int n = n0 + wr * 16 + gid + rh * 8;
                    size_t idx = ((size_t)bb * NSP + n) * CDIM + o;
                    if (z == 0) {
                        f0 *= LOG2E; f1 *= LOG2E;
                        __half h0 = __float2half_rn(f0);
                        __half h1 = __float2half_rn(f1);
                        __half l0 = __float2half_rn(f0 - __half2float(h0));
                        __half l1 = __float2half_rn(f1 - __half2float(h1));
                        *(u32*)&g_Qh1[idx] =
                            (u32)__half_as_ushort(h0) | ((u32)__half_as_ushort(h1) << 16);
                        *(u32*)&g_Qh2[idx] =
                            (u32)__half_as_ushort(l0) | ((u32)__half_as_ushort(l1) << 16);
                    } else {
                        __half h0 = __float2half_rn(f0);
                        __half h1 = __float2half_rn(f1);
                        *(u32*)&g_Kh[idx] =
                            (u32)__half_as_ushort(h0) | ((u32)__half_as_ushort(h1) << 16);
                    }
                }
            }
        } else {
            float* st = (float*)(smem + PJ_ST);
            #pragma unroll
            for (int t = 0; t < 4; t++) {
                int ol = wc * 32 + t * 8 + 2 * tig;
                float b0 = bias_s[oq * 64 + ol], b1 = bias_s[oq * 64 + ol + 1];
                #pragma unroll
                for (int rh = 0; rh < 2; rh++) {
                    int nl = wr * 16 + gid + rh * 8;
                    st[ol * 68 + nl]       = D[t][2 * rh + 0] + b0;
                    st[(ol + 1) * 68 + nl] = D[t][2 * rh + 1] + b1;
                }
            }
            __syncthreads();
            int ol = tid >> 2, nch = (tid & 3) * 16;
            float* dst = g_V + ((size_t)bb * CDIM + oq * 64 + ol) * NSP + n0 + nch;
            #pragma unroll
            for (int k = 0; k < 4; k++) {
                float4 v;
                v.x = tf32r(st[ol * 68 + nch + 4 * k + 0]);
                v.y = tf32r(st[ol * 68 + nch + 4 * k + 1]);
                v.z = tf32r(st[ol * 68 + nch + 4 * k + 2]);
                v.w = tf32r(st[ol * 68 + nch + 4 * k + 3]);
                *(float4*)(dst + 4 * k) = v;
            }
        }
    }
}

// ---------------------------------------------------------------------------
// Kernel D: mma.sync flash attention. fp16 2-pass QK, tf32 PV, pair barriers.
// ---------------------------------------------------------------------------
#define SQ1 0
#define SQ2 33792
#define SK  67584
#define SV  101376
#define SP  171008
#define SLR 188416
#define SM_TOTAL 188672
#define QK_STR 528
#define VP_STR 272
#define OT_STR 258

__global__ __launch_bounds__(256, 1) void attn_kernel(
    const float* __restrict__ x, float* __restrict__ out)
{
    extern __shared__ __align__(16) char smem[];
    const u32 sb = smem_u32(smem);
    const int tid = threadIdx.x;
    const int lane = tid & 31;
    const int warp = tid >> 5;
    const int wr = warp >> 1, wc = warp & 1;
    const int gid = lane >> 2, tig = lane & 3;
    const int i0 = wr * 16;
    const int j0 = wc * 32;
    const int bb = blockIdx.y;
    const int n0 = blockIdx.x * BQ;

    float* lrow = (float*)(smem + SLR);
    if (tid < 64) lrow[tid] = 0.0f;

    const __half* q1g = g_Qh1 + ((size_t)bb * NSP + n0) * CDIM;
    const __half* q2g = g_Qh2 + ((size_t)bb * NSP + n0) * CDIM;
    const __half* khg = g_Kh  + (size_t)bb * NSP * CDIM;
    const float*  vg  = g_V   + (size_t)bb * CDIM * NSP;

    #pragma unroll
    for (int it = 0; it < 8; it++) {
        int idx = it * 256 + tid;
        int i = idx >> 5, ch = idx & 31;
        uint4 v1 = *(const uint4*)&q1g[(size_t)i * CDIM + ch * 8];
        uint4 v2 = *(const uint4*)&q2g[(size_t)i * CDIM + ch * 8];
        sts_v4(sb + SQ1 + i * QK_STR + ch * 16, v1);
        sts_v4(sb + SQ2 + i * QK_STR + ch * 16, v2);
    }

    auto issueK = [&](int k0) {
        #pragma unroll
        for (int it = 0; it < 8; it++) {
            int idx = it * 256 + tid;
            int j = idx >> 5, ch = idx & 31;
            CP16(sb + SK + j * QK_STR + ch * 16, &khg[(size_t)(k0 + j) * CDIM + ch * 8]);
        }
        CPCOMMIT();
    };
    auto issueV = [&](int k0) {
        #pragma unroll
        for (int it = 0; it < 16; it++) {
            int idx = it * 256 + tid;
            int c = idx >> 4, ch = idx & 15;
            CP16(sb + SV + c * VP_STR + ch * 16, &vg[(size_t)c * NSP + k0 + ch * 4]);
        }
        CPCOMMIT();
    };

    issueK(0);
    issueV(0);

    const u32 aBase1 = sb + SQ1 + (i0 + (lane & 15)) * QK_STR + (lane >> 4) * 16;
    const u32 aBase2 = sb + SQ2 + (i0 + (lane & 15)) * QK_STR + (lane >> 4) * 16;
    const int bRow = j0 + (lane & 7) + ((lane >> 4) << 3);
    const u32 bOff = ((lane >> 3) & 1) * 16;
    const u32 bBase = sb + SK + bRow * QK_STR + bOff;

    float O[16][4];
    #pragma unroll
    for (int t = 0; t < 16; t++)
        #pragma unroll
        for (int e = 0; e < 4; e++) O[t][e] = 0.0f;
    float lsum0 = 0.0f, lsum1 = 0.0f;

    for (int kt = 0; kt < NK; kt++) {
        CPWAIT(1);                  // K(kt) ready
        __syncthreads();

        // ---- S = (q1+q2) * k, fp16 2-pass ----
        float S[4][4];
        #pragma unroll
        for (int t = 0; t < 4; t++)
            #pragma unroll
            for (int e = 0; e < 4; e++) S[t][e] = 0.0f;

        #pragma unroll
        for (int kk = 0; kk < 16; kk++) {
            u32 aq1[4], aq2[4], bk[8];
            ldsm4(aq1, aBase1 + kk * 32);
            ldsm4(aq2, aBase2 + kk * 32);
            ldsm4(bk,     bBase + kk * 32);
            ldsm4(bk + 4, bBase + 16 * QK_STR + kk * 32);
            #pragma unroll
            for (int t = 0; t < 4; t++) {
                mma_f16(S[t], aq1, bk[2 * t], bk[2 * t + 1]);
                mma_f16(S[t], aq2, bk[2 * t], bk[2 * t + 1]);
            }
        }

        CPWAIT(0);                  // V(kt) ready; K fully read
        __syncthreads();
        issueK(((kt + 1) & (NK - 1)) * BK);

        // ---- P = exp2(S) (max-free), tf32 to smem ----
        #pragma unroll
        for (int t = 0; t < 4; t++) {
            int jc = j0 + 8 * t + 2 * tig;
            float p0 = ex2f(S[t][0]), p1 = ex2f(S[t][1]);
            float p2 = ex2f(S[t][2]), p3 = ex2f(S[t][3]);
            lsum0 += p0 + p1;
            lsum1 += p2 + p3;
            sts_v2f(sb + SP + ((i0 + gid) * 68 + jc) * 4, tf32r(p0), tf32r(p1));
            sts_v2f(sb + SP + ((i0 + gid + 8) * 68 + jc) * 4, tf32r(p2), tf32r(p3));
        }
        BAR_PAIR(1 + wr);           // P visible within the wr pair only

        // ---- O += P @ V^T, tf32 ----
        const u32 pB = sb + SP + ((i0 + gid) * 68 + tig) * 4;
        const u32 vB = sb + SV + ((wc * 128 + gid) * 68 + tig) * 4;
        #pragma unroll
        for (int ks = 0; ks < 8; ks++) {
            u32 pa = pB + ks * 32;
            u32 a0 = lds_u32(pa);
            u32 a1 = lds_u32(pa + 8 * VP_STR);
            u32 a2 = lds_u32(pa + 16);
            u32 a3 = lds_u32(pa + 8 * VP_STR + 16);
            #pragma unroll
            for (int t = 0; t < 16; t++) {
                u32 vb = vB + t * 8 * VP_STR + ks * 32;
                u32 b0 = lds_u32(vb);
                u32 b1 = lds_u32(vb + 16);
                mma_tf32(O[t], a0, a1, a2, a3, b0, b1);
            }
        }
        __syncthreads();            // V (and P) fully read
        if (kt + 1 < NK) issueV((kt + 1) * BK);
    }

    CPWAIT(0);

    lsum0 += __shfl_xor_sync(0xffffffffu, lsum0, 1);
    lsum0 += __shfl_xor_sync(0xffffffffu, lsum0, 2);
    lsum1 += __shfl_xor_sync(0xffffffffu, lsum1, 1);
    lsum1 += __shfl_xor_sync(0xffffffffu, lsum1, 2);
    if (tig == 0) {
        atomicAdd(&lrow[i0 + gid], lsum0);
        atomicAdd(&lrow[i0 + gid + 8], lsum1);
    }
    __syncthreads();

    #pragma unroll
    for (int t = 0; t < 16; t++) {
        int c = wc * 128 + 8 * t + 2 * tig;
        sts_v2f(sb + SV + ((i0 + gid) * OT_STR + c) * 4, O[t][0], O[t][1]);
        sts_v2f(sb + SV + ((i0 + gid + 8) * OT_STR + c) * 4, O[t][2], O[t][3]);
    }
    __syncthreads();

    const float* xb = x + (size_t)bb * CDIM * NSP;
    float* ob = out + (size_t)bb * CDIM * NSP;
    const int i = tid & 63;
    const int cg = tid >> 6;
    const float invl = 1.0f / lrow[i];
    #pragma unroll 4
    for (int cc = 0; cc < 64; cc++) {
        int c = cc * 4 + cg;
        float ov = lds_f32(sb + SV + (i * OT_STR + c) * 4);
        size_t g = (size_t)c * NSP + n0 + i;
        ob[g] = ov * invl + xb[g];
    }
}

// ---------------------------------------------------------------------------
extern "C" void kernel_launch(void* const* d_in, const int* in_sizes, int n_in,
                              void* d_out, int out_size)
{
    const float* x    = (const float*)d_in[0];
    const float* attr = (const float*)d_in[1];
    const float* Wq   = (const float*)d_in[2];
    const float* bq   = (const float*)d_in[3];
    const float* Wk   = (const float*)d_in[4];
    const float* bk   = (const float*)d_in[5];
    const float* Wv   = (const float*)d_in[6];
    const float* bv   = (const float*)d_in[7];
    float* out = (float*)d_out;

    cudaFuncSetAttribute(proj_mma,
                         cudaFuncAttributeMaxDynamicSharedMemorySize, PJ_TOTAL);
    cudaFuncSetAttribute(attn_kernel,
                         cudaFuncAttributeMaxDynamicSharedMemorySize, SM_TOTAL);

    split_w<<<768, 256>>>(Wq, Wk, Wv);
    split_x<<<dim3(NSP / 32, CDIM / 32, NB * 2), 256>>>(x, attr);
    proj_mma<<<dim3(NSP / 64, NB, 3), 256, PJ_TOTAL>>>(bq, bk, bv);
    attn_kernel<<<dim3(NSP / BQ, NB), 256, SM_TOTAL>>>(x, out);
}